// round 1
// baseline (speedup 1.0000x reference)
#include <cuda_runtime.h>

// ---------------- problem constants ----------------
#define NMAX 50000
#define EMAX 800000
#define MKER 27          // 3^3 spline kernels
#define C    64          // hidden channels
#define YSTR (MKER * C)  // 1728

// ---------------- static scratch (no runtime allocation) ----------------
__device__ float g_y[(long long)NMAX * YSTR];   // 345.6 MB transformed features
__device__ float g_agg[NMAX * C];               // 12.8 MB aggregation buffer
__device__ float g_h[NMAX * C];                 // 12.8 MB hidden state
__device__ int   g_deg[NMAX];

// ---------------- helpers ----------------
__device__ __forceinline__ float2 ffma2(float2 a, float2 b, float2 c) {
    float2 d;
    asm("fma.rn.f32x2 %0, %1, %2, %3;"
        : "=l"(*reinterpret_cast<unsigned long long*>(&d))
        : "l"(*reinterpret_cast<unsigned long long*>(&a)),
          "l"(*reinterpret_cast<unsigned long long*>(&b)),
          "l"(*reinterpret_cast<unsigned long long*>(&c)));
    return d;
}

// degree-1 open B-spline basis: 8 corner weights + flat kernel indices
__device__ __forceinline__ void basis8(const float* __restrict__ ea,
                                       float w[8], int kk[8]) {
    float p0 = ea[0] * 2.0f, p1 = ea[1] * 2.0f, p2 = ea[2] * 2.0f;
    float f0 = fminf(fmaxf(floorf(p0), 0.f), 1.f);
    float f1 = fminf(fmaxf(floorf(p1), 0.f), 1.f);
    float f2 = fminf(fmaxf(floorf(p2), 0.f), 1.f);
    float u0 = p0 - f0, u1 = p1 - f1, u2 = p2 - f2;
    int   i0 = (int)f0, i1 = (int)f1, i2 = (int)f2;
    int   base = i0 + 3 * i1 + 9 * i2;
#pragma unroll
    for (int b = 0; b < 8; b++) {
        float a0 = (b & 1) ? u0 : 1.f - u0;
        float a1 = (b & 2) ? u1 : 1.f - u1;
        float a2 = (b & 4) ? u2 : 1.f - u2;
        w[b]  = a0 * a1 * a2;
        kk[b] = base + (b & 1) + 3 * ((b >> 1) & 1) + 9 * ((b >> 2) & 1);
    }
}

// ---------------- trivial kernels ----------------
__global__ void zero_deg_kernel(int N) {
    int i = blockIdx.x * blockDim.x + threadIdx.x;
    if (i < N) g_deg[i] = 0;
}
__global__ void hist_kernel(const int* __restrict__ dst, int E) {
    int i = blockIdx.x * blockDim.x + threadIdx.x;
    if (i < E) atomicAdd(&g_deg[dst[i]], 1);
}
__global__ void zero_agg_kernel(int n) {
    int i = blockIdx.x * blockDim.x + threadIdx.x;
    if (i < n) g_agg[i] = 0.f;
}

// ---------------- layer 0 edge kernel (Cin = 3, W0 read directly) ----------------
__global__ void edge0_kernel(const float* __restrict__ x,
                             const int* __restrict__ src,
                             const int* __restrict__ dst,
                             const float* __restrict__ ea,
                             const float* __restrict__ W0, int E) {
    int e    = (blockIdx.x * blockDim.x + threadIdx.x) >> 5;
    int lane = threadIdx.x & 31;
    if (e >= E) return;
    float w[8]; int kk[8];
    basis8(ea + 3 * e, w, kk);
    int   s  = src[e];
    float x0 = __ldg(x + 3 * s), x1 = __ldg(x + 3 * s + 1), x2 = __ldg(x + 3 * s + 2);
    float2 msg = make_float2(0.f, 0.f);
#pragma unroll
    for (int c = 0; c < 8; c++) {
        const float* Wk = W0 + kk[c] * (3 * C) + 2 * lane;
        float2 a = __ldg((const float2*)(Wk));
        float2 b = __ldg((const float2*)(Wk + C));
        float2 d = __ldg((const float2*)(Wk + 2 * C));
        float wx0 = w[c] * x0, wx1 = w[c] * x1, wx2 = w[c] * x2;
        msg.x += wx0 * a.x + wx1 * b.x + wx2 * d.x;
        msg.y += wx0 * a.y + wx1 * b.y + wx2 * d.y;
    }
    float* ap = &g_agg[dst[e] * C + 2 * lane];
    atomicAdd(ap,     msg.x);
    atomicAdd(ap + 1, msg.y);
}

// ---------------- transform: y[n, m*64+co] = sum_ci h[n,ci] * W[m,ci,co] ----------
// block = 256 threads, 64 nodes per block, one m per block.
// Wt held transposed in smem (stride 68 -> 4-way max conflict, float4-aligned)
// so the dot product vectorizes over ci pairs via fma.rn.f32x2.
#define T_NODES 64
#define WT_STR  68
__global__ void __launch_bounds__(256)
transform_kernel(const float* __restrict__ h, const float* __restrict__ W, int N) {
    __shared__ float Wt[C * WT_STR];   // [co][ci], padded
    __shared__ float hs[T_NODES * C];  // [n][ci]
    int m   = blockIdx.y;
    int n0  = blockIdx.x * T_NODES;
    int tid = threadIdx.x;

    const float* Wm = W + m * C * C;
    for (int i = tid; i < C * C; i += 256) {
        int ci = i >> 6, co = i & 63;
        Wt[co * WT_STR + ci] = Wm[i];
    }
    for (int i = tid; i < T_NODES * C; i += 256) {
        int n = n0 + (i >> 6);
        hs[i] = (n < N) ? h[n * C + (i & 63)] : 0.f;
    }
    __syncthreads();

    int co = tid & 63;
    int nb = (tid >> 6) * 16;   // 4 groups of 16 nodes

    float2 acc[16];
#pragma unroll
    for (int j = 0; j < 16; j++) acc[j] = make_float2(0.f, 0.f);

#pragma unroll
    for (int ci = 0; ci < C; ci += 4) {
        float4 wv  = *(const float4*)&Wt[co * WT_STR + ci];
        float2 w01 = make_float2(wv.x, wv.y);
        float2 w23 = make_float2(wv.z, wv.w);
#pragma unroll
        for (int j = 0; j < 16; j++) {
            float4 hv = *(const float4*)&hs[(nb + j) * C + ci];   // warp-broadcast
            acc[j] = ffma2(make_float2(hv.x, hv.y), w01, acc[j]);
            acc[j] = ffma2(make_float2(hv.z, hv.w), w23, acc[j]);
        }
    }
#pragma unroll
    for (int j = 0; j < 16; j++) {
        int n = n0 + nb + j;
        if (n < N) g_y[(long long)n * YSTR + m * C + co] = acc[j].x + acc[j].y;
    }
}

// ---------------- edge gather (layers 1,2): one warp per edge ----------------
__global__ void edge_gather_kernel(const int* __restrict__ src,
                                   const int* __restrict__ dst,
                                   const float* __restrict__ ea, int E) {
    int e    = (blockIdx.x * blockDim.x + threadIdx.x) >> 5;
    int lane = threadIdx.x & 31;
    if (e >= E) return;
    float w[8]; int kk[8];
    basis8(ea + 3 * e, w, kk);
    int s = src[e];
    const float* yb = g_y + (long long)s * YSTR + 2 * lane;
    float2 msg = make_float2(0.f, 0.f);
#pragma unroll
    for (int c = 0; c < 8; c++) {
        float2 v = __ldg((const float2*)(yb + kk[c] * C));   // 256B coalesced row
        msg.x += w[c] * v.x;
        msg.y += w[c] * v.y;
    }
    float* ap = &g_agg[dst[e] * C + 2 * lane];
    atomicAdd(ap,     msg.x);
    atomicAdd(ap + 1, msg.y);
}

// ---------------- finalize: out = relu(agg/deg + h@Wr + b) --------------------
// block = 256 threads = 4 nodes x 64 co. Safe in-place (block-local rows).
__global__ void finalize_kernel(const float* __restrict__ hin,
                                const float* __restrict__ Wr,
                                const float* __restrict__ bias,
                                float* __restrict__ hout, int N, int Cin) {
    __shared__ float hs[4 * C];
    int n0  = blockIdx.x * 4;
    int tid = threadIdx.x;
    int j   = tid >> 6, co = tid & 63;
    for (int i = tid; i < 4 * Cin; i += 256) {
        int n = n0 + i / Cin;
        hs[i] = (n < N) ? hin[n * Cin + i % Cin] : 0.f;
    }
    __syncthreads();
    int n = n0 + j;
    if (n >= N) return;
    float acc = __ldg(bias + co);
    for (int ci = 0; ci < Cin; ci++)
        acc += hs[j * Cin + ci] * __ldg(Wr + ci * C + co);
    int   dg  = g_deg[n];
    float inv = 1.f / (float)(dg > 0 ? dg : 1);
    float v   = g_agg[n * C + co] * inv + acc;
    hout[n * C + co] = fmaxf(v, 0.f);
}

// ---------------- launch ----------------
extern "C" void kernel_launch(void* const* d_in, const int* in_sizes, int n_in,
                              void* d_out, int out_size) {
    const float* x     = (const float*)d_in[0];
    const int*   ei    = (const int*)d_in[1];
    const float* ea    = (const float*)d_in[2];
    const float* W0    = (const float*)d_in[3];
    const float* root0 = (const float*)d_in[4];
    const float* b0    = (const float*)d_in[5];
    const float* W1    = (const float*)d_in[6];
    const float* root1 = (const float*)d_in[7];
    const float* b1    = (const float*)d_in[8];
    const float* W2    = (const float*)d_in[9];
    const float* root2 = (const float*)d_in[10];
    const float* b2    = (const float*)d_in[11];
    float* out = (float*)d_out;

    int N = in_sizes[0] / 3;
    int E = in_sizes[1] / 2;
    const int* src = ei;
    const int* dst = ei + E;

    float* hP;
    cudaGetSymbolAddress((void**)&hP, g_h);

    int edgeBlocks = (E * 32 + 255) / 256;
    int aggBlocks  = (N * C + 511) / 512;
    dim3 tGrid((N + T_NODES - 1) / T_NODES, MKER);

    // degree histogram (used by all layers)
    zero_deg_kernel<<<(N + 255) / 256, 256>>>(N);
    hist_kernel<<<(E + 255) / 256, 256>>>(dst, E);

    // ---- layer 0 (Cin = 3): direct per-edge messages from x and W0 ----
    zero_agg_kernel<<<aggBlocks, 512>>>(N * C);
    edge0_kernel<<<edgeBlocks, 256>>>(x, src, dst, ea, W0, E);
    finalize_kernel<<<(N + 3) / 4, 256>>>(x, root0, b0, hP, N, 3);

    // ---- layer 1 ----
    transform_kernel<<<tGrid, 256>>>(hP, W1, N);
    zero_agg_kernel<<<aggBlocks, 512>>>(N * C);
    edge_gather_kernel<<<edgeBlocks, 256>>>(src, dst, ea, E);
    finalize_kernel<<<(N + 3) / 4, 256>>>(hP, root1, b1, hP, N, C);

    // ---- layer 2 ----
    transform_kernel<<<tGrid, 256>>>(hP, W2, N);
    zero_agg_kernel<<<aggBlocks, 512>>>(N * C);
    edge_gather_kernel<<<edgeBlocks, 256>>>(src, dst, ea, E);
    finalize_kernel<<<(N + 3) / 4, 256>>>(hP, root2, b2, out, N, C);
}

// round 2
// speedup vs baseline: 1.0960x; 1.0960x over previous
#include <cuda_runtime.h>

// ---------------- problem constants ----------------
#define NMAX 50000
#define EMAX 800000
#define MKER 27            // 3^3 spline kernels
#define C    64            // hidden channels
#define YROWS 28           // 27 spline + 1 root row
#define YSTR (YROWS * C)   // 1792
#define SSTR 108           // 27 * 4 (ci0,ci1,ci2,pad) layer-0 agg row

// ---------------- static scratch ----------------
__device__ float  g_y[(size_t)NMAX * YSTR];   // 358 MB transformed features
__device__ float  g_h[NMAX * C];              // hidden state
__device__ float  g_S[NMAX * SSTR];           // layer-0 input-space agg (21.6 MB)
__device__ float4 g_rec[EMAX];                // CSR edge records: (src, ea0, ea1, ea2)
__device__ int    g_rowptr[NMAX + 1];
__device__ int    g_cursor[NMAX];
__device__ int    g_deg[NMAX];

// ---------------- helpers ----------------
__device__ __forceinline__ float2 ffma2(float2 a, float2 b, float2 c) {
    float2 d;
    asm("fma.rn.f32x2 %0, %1, %2, %3;"
        : "=l"(*reinterpret_cast<unsigned long long*>(&d))
        : "l"(*reinterpret_cast<unsigned long long*>(&a)),
          "l"(*reinterpret_cast<unsigned long long*>(&b)),
          "l"(*reinterpret_cast<unsigned long long*>(&c)));
    return d;
}

__device__ __forceinline__ void basis8(float e0, float e1, float e2,
                                       float w[8], int kk[8]) {
    float p0 = e0 * 2.0f, p1 = e1 * 2.0f, p2 = e2 * 2.0f;
    float f0 = fminf(fmaxf(floorf(p0), 0.f), 1.f);
    float f1 = fminf(fmaxf(floorf(p1), 0.f), 1.f);
    float f2 = fminf(fmaxf(floorf(p2), 0.f), 1.f);
    float u0 = p0 - f0, u1 = p1 - f1, u2 = p2 - f2;
    int base = (int)f0 + 3 * (int)f1 + 9 * (int)f2;
#pragma unroll
    for (int b = 0; b < 8; b++) {
        float a0 = (b & 1) ? u0 : 1.f - u0;
        float a1 = (b & 2) ? u1 : 1.f - u1;
        float a2 = (b & 4) ? u2 : 1.f - u2;
        w[b]  = a0 * a1 * a2;
        kk[b] = base + (b & 1) + 3 * ((b >> 1) & 1) + 9 * ((b >> 2) & 1);
    }
}

// ---------------- CSR build ----------------
__global__ void zero_deg_kernel(int N) {
    int i = blockIdx.x * blockDim.x + threadIdx.x;
    if (i < N) g_deg[i] = 0;
}
__global__ void hist_kernel(const int* __restrict__ dst, int E) {
    int i = blockIdx.x * blockDim.x + threadIdx.x;
    if (i < E) atomicAdd(&g_deg[dst[i]], 1);
}
__global__ void zero_S_kernel(int n) {
    int i = blockIdx.x * blockDim.x + threadIdx.x;
    if (i < n) g_S[i] = 0.f;
}
// single-block exclusive scan of g_deg -> g_rowptr (and g_cursor copy)
__global__ void scan_kernel(int N) {
    __shared__ int ssum[1024];
    int tid = threadIdx.x;
    int chunk = (N + 1023) / 1024;
    int beg = tid * chunk;
    int end = min(beg + chunk, N);
    int s = 0;
    for (int i = beg; i < end; i++) s += g_deg[i];
    ssum[tid] = s;
    __syncthreads();
    for (int off = 1; off < 1024; off <<= 1) {
        int v = 0;
        if (tid >= off) v = ssum[tid - off];
        __syncthreads();
        if (tid >= off) ssum[tid] += v;
        __syncthreads();
    }
    int run = (tid == 0) ? 0 : ssum[tid - 1];
    for (int i = beg; i < end; i++) {
        g_rowptr[i] = run;
        g_cursor[i] = run;
        run += g_deg[i];
    }
    if (tid == 1023) g_rowptr[N] = ssum[1023];
}

// edge pass: write CSR record + layer-0 input-space scatter (float4 RED)
__global__ void build_kernel(const int* __restrict__ src,
                             const int* __restrict__ dst,
                             const float* __restrict__ ea,
                             const float* __restrict__ x, int E) {
    int e = blockIdx.x * blockDim.x + threadIdx.x;
    if (e >= E) return;
    int s = src[e], d = dst[e];
    float e0 = ea[3 * e], e1 = ea[3 * e + 1], e2 = ea[3 * e + 2];

    int pos = atomicAdd(&g_cursor[d], 1);
    g_rec[pos] = make_float4(__int_as_float(s), e0, e1, e2);

    float w[8]; int kk[8];
    basis8(e0, e1, e2, w, kk);
    float x0 = __ldg(x + 3 * s), x1 = __ldg(x + 3 * s + 1), x2 = __ldg(x + 3 * s + 2);
    float4* Sb = (float4*)(g_S + (size_t)d * SSTR);
#pragma unroll
    for (int c = 0; c < 8; c++)
        atomicAdd(Sb + kk[c], make_float4(w[c] * x0, w[c] * x1, w[c] * x2, 0.f));
}

// ---------------- layer 0 finalize: h = relu(S@W0/deg + x@root0 + b0) --------
__global__ void __launch_bounds__(256)
l0_kernel(const float* __restrict__ x, const float* __restrict__ W0,
          const float* __restrict__ root0, const float* __restrict__ b0, int N) {
    int n    = (blockIdx.x * blockDim.x + threadIdx.x) >> 5;
    int lane = threadIdx.x & 31;
    if (n >= N) return;
    const float* Sr = g_S + (size_t)n * SSTR;
    float sA = Sr[lane];
    float sB = Sr[32 + lane];
    float sC = Sr[64 + lane];
    float sD = (lane < 12) ? Sr[96 + lane] : 0.f;

    float2 acc = make_float2(0.f, 0.f);
#pragma unroll
    for (int m = 0; m < MKER; m++) {
#pragma unroll
        for (int ci = 0; ci < 3; ci++) {
            int s  = m * 4 + ci;
            int r  = s >> 5, sl = s & 31;
            float v = (r == 0) ? __shfl_sync(0xffffffffu, sA, sl)
                    : (r == 1) ? __shfl_sync(0xffffffffu, sB, sl)
                    : (r == 2) ? __shfl_sync(0xffffffffu, sC, sl)
                               : __shfl_sync(0xffffffffu, sD, sl);
            float2 wv = __ldg((const float2*)(W0 + (m * 3 + ci) * C) + lane);
            acc.x += v * wv.x;
            acc.y += v * wv.y;
        }
    }
    int   dg  = g_rowptr[n + 1] - g_rowptr[n];
    float inv = 1.f / (float)(dg > 0 ? dg : 1);
    float xv  = (lane < 3) ? __ldg(x + 3 * n + lane) : 0.f;
    float x0  = __shfl_sync(0xffffffffu, xv, 0);
    float x1  = __shfl_sync(0xffffffffu, xv, 1);
    float x2  = __shfl_sync(0xffffffffu, xv, 2);
    float2 r0 = __ldg((const float2*)(root0)         + lane);
    float2 r1 = __ldg((const float2*)(root0 + C)     + lane);
    float2 r2 = __ldg((const float2*)(root0 + 2 * C) + lane);
    float2 bb = __ldg((const float2*)(b0)            + lane);
    float2 res;
    res.x = fmaxf(acc.x * inv + x0 * r0.x + x1 * r1.x + x2 * r2.x + bb.x, 0.f);
    res.y = fmaxf(acc.y * inv + x0 * r0.y + x1 * r1.y + x2 * r2.y + bb.y, 0.f);
    ((float2*)g_h)[(size_t)n * 32 + lane] = res;
}

// ---------------- transform: y[n, m*64+co] = sum_ci h[n,ci] * W[m,ci,co] ------
// m in [0,27) uses W; m == 27 produces the root-weight row (h @ Wr).
#define T_NODES 64
#define WT_STR  68
__global__ void __launch_bounds__(256)
transform_kernel(const float* __restrict__ h, const float* __restrict__ W,
                 const float* __restrict__ Wr, int N) {
    __shared__ float Wt[C * WT_STR];   // [co][ci], padded
    __shared__ float hs[T_NODES * C];  // [n][ci]
    int m   = blockIdx.y;
    int n0  = blockIdx.x * T_NODES;
    int tid = threadIdx.x;

    const float* Wm = (m < MKER) ? (W + m * C * C) : Wr;
    for (int i = tid; i < C * C; i += 256) {
        int ci = i >> 6, co = i & 63;
        Wt[co * WT_STR + ci] = Wm[i];
    }
    for (int i = tid; i < T_NODES * C; i += 256) {
        int n = n0 + (i >> 6);
        hs[i] = (n < N) ? h[(size_t)n * C + (i & 63)] : 0.f;
    }
    __syncthreads();

    int co = tid & 63;
    int nb = (tid >> 6) * 16;

    float2 acc[16];
#pragma unroll
    for (int j = 0; j < 16; j++) acc[j] = make_float2(0.f, 0.f);

#pragma unroll
    for (int ci = 0; ci < C; ci += 4) {
        float4 wv  = *(const float4*)&Wt[co * WT_STR + ci];
        float2 w01 = make_float2(wv.x, wv.y);
        float2 w23 = make_float2(wv.z, wv.w);
#pragma unroll
        for (int j = 0; j < 16; j++) {
            float4 hv = *(const float4*)&hs[(nb + j) * C + ci];
            acc[j] = ffma2(make_float2(hv.x, hv.y), w01, acc[j]);
            acc[j] = ffma2(make_float2(hv.z, hv.w), w23, acc[j]);
        }
    }
#pragma unroll
    for (int j = 0; j < 16; j++) {
        int n = n0 + nb + j;
        if (n < N) g_y[(size_t)n * YSTR + m * C + co] = acc[j].x + acc[j].y;
    }
}

// ---------------- node kernel (layers 1,2): warp per dst node, no atomics ----
__global__ void __launch_bounds__(256)
node_kernel(const float* __restrict__ bias, float* __restrict__ h_out, int N) {
    int n    = (blockIdx.x * blockDim.x + threadIdx.x) >> 5;
    int lane = threadIdx.x & 31;
    if (n >= N) return;
    int beg = g_rowptr[n], end = g_rowptr[n + 1];

    float2 acc = make_float2(0.f, 0.f);
    for (int e = beg; e < end; e++) {
        float4 r = __ldg(&g_rec[e]);          // uniform across warp
        int s = __float_as_int(r.x);
        float w[8]; int kk[8];
        basis8(r.y, r.z, r.w, w, kk);
        const float* yb = g_y + (size_t)s * YSTR;
#pragma unroll
        for (int c = 0; c < 8; c++) {
            float2 v = __ldg((const float2*)(yb + kk[c] * C) + lane);  // 256B coalesced
            acc.x += w[c] * v.x;
            acc.y += w[c] * v.y;
        }
    }
    int   dg  = end - beg;
    float inv = 1.f / (float)(dg > 0 ? dg : 1);
    float2 rt = __ldg((const float2*)(g_y + (size_t)n * YSTR + MKER * C) + lane);
    float2 bb = __ldg((const float2*)bias + lane);
    float2 res;
    res.x = fmaxf(acc.x * inv + rt.x + bb.x, 0.f);
    res.y = fmaxf(acc.y * inv + rt.y + bb.y, 0.f);
    ((float2*)h_out)[(size_t)n * 32 + lane] = res;
}

// ---------------- launch ----------------
extern "C" void kernel_launch(void* const* d_in, const int* in_sizes, int n_in,
                              void* d_out, int out_size) {
    const float* x     = (const float*)d_in[0];
    const int*   ei    = (const int*)d_in[1];
    const float* ea    = (const float*)d_in[2];
    const float* W0    = (const float*)d_in[3];
    const float* root0 = (const float*)d_in[4];
    const float* b0    = (const float*)d_in[5];
    const float* W1    = (const float*)d_in[6];
    const float* root1 = (const float*)d_in[7];
    const float* b1    = (const float*)d_in[8];
    const float* W2    = (const float*)d_in[9];
    const float* root2 = (const float*)d_in[10];
    const float* b2    = (const float*)d_in[11];
    float* out = (float*)d_out;

    int N = in_sizes[0] / 3;
    int E = in_sizes[1] / 2;
    const int* src = ei;
    const int* dst = ei + E;

    float* hP;
    cudaGetSymbolAddress((void**)&hP, g_h);

    int nodeBlocks = (N * 32 + 255) / 256;
    dim3 tGrid((N + T_NODES - 1) / T_NODES, YROWS);

    // ---- CSR + layer-0 scatter (one edge pass) ----
    zero_deg_kernel<<<(N + 255) / 256, 256>>>(N);
    hist_kernel<<<(E + 255) / 256, 256>>>(dst, E);
    scan_kernel<<<1, 1024>>>(N);
    zero_S_kernel<<<(N * SSTR + 255) / 256, 256>>>(N * SSTR);
    build_kernel<<<(E + 255) / 256, 256>>>(src, dst, ea, x, E);

    // ---- layer 0 ----
    l0_kernel<<<nodeBlocks, 256>>>(x, W0, root0, b0, N);

    // ---- layer 1 ----
    transform_kernel<<<tGrid, 256>>>(hP, W1, root1, N);
    node_kernel<<<nodeBlocks, 256>>>(b1, hP, N);

    // ---- layer 2 ----
    transform_kernel<<<tGrid, 256>>>(hP, W2, root2, N);
    node_kernel<<<nodeBlocks, 256>>>(b2, out, N);
}

// round 3
// speedup vs baseline: 1.1914x; 1.0871x over previous
#include <cuda_runtime.h>
#include <cuda_fp16.h>

// ---------------- problem constants ----------------
#define NMAX 50000
#define EMAX 800000
#define MKER 27            // 3^3 spline kernels
#define C    64            // hidden channels
#define YSTR (MKER * C)    // 1728 halves per node
#define SSTR 108           // 27 * 4 (ci0,ci1,ci2,pad) layer-0 agg row

// ---------------- static scratch ----------------
__device__ __half g_y[(size_t)NMAX * YSTR];   // 172.8 MB transformed features (fp16)
__device__ float  g_root[NMAX * C];           // fp32 root-weight term h @ Wr
__device__ float  g_h[NMAX * C];              // hidden state
__device__ float  g_S[NMAX * SSTR];           // layer-0 input-space agg (21.6 MB)
__device__ float4 g_rec[EMAX];                // CSR edge records: (src, ea0, ea1, ea2)
__device__ int    g_rowptr[NMAX + 1];
__device__ int    g_cursor[NMAX];
__device__ int    g_deg[NMAX];

// ---------------- helpers ----------------
__device__ __forceinline__ float2 ffma2(float2 a, float2 b, float2 c) {
    float2 d;
    asm("fma.rn.f32x2 %0, %1, %2, %3;"
        : "=l"(*reinterpret_cast<unsigned long long*>(&d))
        : "l"(*reinterpret_cast<unsigned long long*>(&a)),
          "l"(*reinterpret_cast<unsigned long long*>(&b)),
          "l"(*reinterpret_cast<unsigned long long*>(&c)));
    return d;
}

__device__ __forceinline__ void basis8(float e0, float e1, float e2,
                                       float w[8], int kk[8]) {
    float p0 = e0 * 2.0f, p1 = e1 * 2.0f, p2 = e2 * 2.0f;
    float f0 = fminf(fmaxf(floorf(p0), 0.f), 1.f);
    float f1 = fminf(fmaxf(floorf(p1), 0.f), 1.f);
    float f2 = fminf(fmaxf(floorf(p2), 0.f), 1.f);
    float u0 = p0 - f0, u1 = p1 - f1, u2 = p2 - f2;
    int base = (int)f0 + 3 * (int)f1 + 9 * (int)f2;
#pragma unroll
    for (int b = 0; b < 8; b++) {
        float a0 = (b & 1) ? u0 : 1.f - u0;
        float a1 = (b & 2) ? u1 : 1.f - u1;
        float a2 = (b & 4) ? u2 : 1.f - u2;
        w[b]  = a0 * a1 * a2;
        kk[b] = base + (b & 1) + 3 * ((b >> 1) & 1) + 9 * ((b >> 2) & 1);
    }
}

// ---------------- CSR build ----------------
// fused zeroing: S (N*SSTR floats) + deg (N ints)
__global__ void zeroAll_kernel(int N) {
    int i = blockIdx.x * blockDim.x + threadIdx.x;
    if (i < N * SSTR) g_S[i] = 0.f;
    if (i < N)        g_deg[i] = 0;
}
__global__ void hist_kernel(const int* __restrict__ dst, int E) {
    int i = blockIdx.x * blockDim.x + threadIdx.x;
    if (i < E) atomicAdd(&g_deg[dst[i]], 1);
}
// single-block exclusive scan of g_deg -> g_rowptr (and g_cursor copy)
__global__ void scan_kernel(int N) {
    __shared__ int ssum[1024];
    int tid = threadIdx.x;
    int chunk = (N + 1023) / 1024;
    int beg = tid * chunk;
    int end = min(beg + chunk, N);
    int s = 0;
    for (int i = beg; i < end; i++) s += g_deg[i];
    ssum[tid] = s;
    __syncthreads();
    for (int off = 1; off < 1024; off <<= 1) {
        int v = 0;
        if (tid >= off) v = ssum[tid - off];
        __syncthreads();
        if (tid >= off) ssum[tid] += v;
        __syncthreads();
    }
    int run = (tid == 0) ? 0 : ssum[tid - 1];
    for (int i = beg; i < end; i++) {
        g_rowptr[i] = run;
        g_cursor[i] = run;
        run += g_deg[i];
    }
    if (tid == 1023) g_rowptr[N] = ssum[1023];
}

// edge pass: write CSR record + layer-0 input-space scatter (float4 RED)
__global__ void build_kernel(const int* __restrict__ src,
                             const int* __restrict__ dst,
                             const float* __restrict__ ea,
                             const float* __restrict__ x, int E) {
    int e = blockIdx.x * blockDim.x + threadIdx.x;
    if (e >= E) return;
    int s = src[e], d = dst[e];
    float e0 = ea[3 * e], e1 = ea[3 * e + 1], e2 = ea[3 * e + 2];

    int pos = atomicAdd(&g_cursor[d], 1);
    g_rec[pos] = make_float4(__int_as_float(s), e0, e1, e2);

    float w[8]; int kk[8];
    basis8(e0, e1, e2, w, kk);
    float x0 = __ldg(x + 3 * s), x1 = __ldg(x + 3 * s + 1), x2 = __ldg(x + 3 * s + 2);
    float4* Sb = (float4*)(g_S + (size_t)d * SSTR);
#pragma unroll
    for (int c = 0; c < 8; c++)
        atomicAdd(Sb + kk[c], make_float4(w[c] * x0, w[c] * x1, w[c] * x2, 0.f));
}

// ---------------- layer 0 finalize: h = relu(S@W0/deg + x@root0 + b0) --------
__global__ void __launch_bounds__(256)
l0_kernel(const float* __restrict__ x, const float* __restrict__ W0,
          const float* __restrict__ root0, const float* __restrict__ b0, int N) {
    int n    = (blockIdx.x * blockDim.x + threadIdx.x) >> 5;
    int lane = threadIdx.x & 31;
    if (n >= N) return;
    const float* Sr = g_S + (size_t)n * SSTR;
    float sA = Sr[lane];
    float sB = Sr[32 + lane];
    float sC = Sr[64 + lane];
    float sD = (lane < 12) ? Sr[96 + lane] : 0.f;

    float2 acc = make_float2(0.f, 0.f);
#pragma unroll
    for (int m = 0; m < MKER; m++) {
#pragma unroll
        for (int ci = 0; ci < 3; ci++) {
            int s  = m * 4 + ci;
            int r  = s >> 5, sl = s & 31;
            float v = (r == 0) ? __shfl_sync(0xffffffffu, sA, sl)
                    : (r == 1) ? __shfl_sync(0xffffffffu, sB, sl)
                    : (r == 2) ? __shfl_sync(0xffffffffu, sC, sl)
                               : __shfl_sync(0xffffffffu, sD, sl);
            float2 wv = __ldg((const float2*)(W0 + (m * 3 + ci) * C) + lane);
            acc.x += v * wv.x;
            acc.y += v * wv.y;
        }
    }
    int   dg  = g_rowptr[n + 1] - g_rowptr[n];
    float inv = 1.f / (float)(dg > 0 ? dg : 1);
    float xv  = (lane < 3) ? __ldg(x + 3 * n + lane) : 0.f;
    float x0  = __shfl_sync(0xffffffffu, xv, 0);
    float x1  = __shfl_sync(0xffffffffu, xv, 1);
    float x2  = __shfl_sync(0xffffffffu, xv, 2);
    float2 r0 = __ldg((const float2*)(root0)         + lane);
    float2 r1 = __ldg((const float2*)(root0 + C)     + lane);
    float2 r2 = __ldg((const float2*)(root0 + 2 * C) + lane);
    float2 bb = __ldg((const float2*)(b0)            + lane);
    float2 res;
    res.x = fmaxf(acc.x * inv + x0 * r0.x + x1 * r1.x + x2 * r2.x + bb.x, 0.f);
    res.y = fmaxf(acc.y * inv + x0 * r0.y + x1 * r1.y + x2 * r2.y + bb.y, 0.f);
    ((float2*)g_h)[(size_t)n * 32 + lane] = res;
}

// ---------------- transform: y[n, m, co] = sum_ci h[n,ci] * W[m,ci,co] --------
// block = 256 threads, 64 nodes/block, grid.y = 28 (27 spline m + root row).
// Each thread owns 2 adjacent co (co0, co0+1) and 8 nodes: every smem hv
// broadcast feeds 4 fma2 -> FFMA2-floor bound, not LDS bound.
// m < 27 stores fp16 into g_y; m == 27 stores fp32 into g_root.
#define T_NODES 64
#define WT_STR  68
__global__ void __launch_bounds__(256)
transform_kernel(const float* __restrict__ h, const float* __restrict__ W,
                 const float* __restrict__ Wr, int N) {
    __shared__ float Wt[C * WT_STR];   // [co][ci], padded stride 68
    __shared__ float hs[T_NODES * C];  // [n][ci]
    int m   = blockIdx.y;
    int n0  = blockIdx.x * T_NODES;
    int tid = threadIdx.x;

    const float* Wm = (m < MKER) ? (W + m * C * C) : Wr;
    for (int i = tid; i < C * C; i += 256) {
        int ci = i >> 6, co = i & 63;
        Wt[co * WT_STR + ci] = Wm[i];
    }
    for (int i = tid; i < T_NODES * C; i += 256) {
        int n = n0 + (i >> 6);
        hs[i] = (n < N) ? h[(size_t)n * C + (i & 63)] : 0.f;
    }
    __syncthreads();

    int co0 = (tid & 31) * 2;        // this thread's co pair
    int nb  = (tid >> 5) * 8;        // 8 groups x 8 nodes

    float2 acc[8][2];
#pragma unroll
    for (int j = 0; j < 8; j++) {
        acc[j][0] = make_float2(0.f, 0.f);
        acc[j][1] = make_float2(0.f, 0.f);
    }

#pragma unroll
    for (int ci = 0; ci < C; ci += 4) {
        float4 wa = *(const float4*)&Wt[co0 * WT_STR + ci];
        float4 wb = *(const float4*)&Wt[(co0 + 1) * WT_STR + ci];
        float2 wa01 = make_float2(wa.x, wa.y), wa23 = make_float2(wa.z, wa.w);
        float2 wb01 = make_float2(wb.x, wb.y), wb23 = make_float2(wb.z, wb.w);
#pragma unroll
        for (int j = 0; j < 8; j++) {
            float4 hv = *(const float4*)&hs[(nb + j) * C + ci];  // warp-broadcast
            float2 h01 = make_float2(hv.x, hv.y), h23 = make_float2(hv.z, hv.w);
            acc[j][0] = ffma2(h01, wa01, acc[j][0]);
            acc[j][0] = ffma2(h23, wa23, acc[j][0]);
            acc[j][1] = ffma2(h01, wb01, acc[j][1]);
            acc[j][1] = ffma2(h23, wb23, acc[j][1]);
        }
    }

#pragma unroll
    for (int j = 0; j < 8; j++) {
        int n = n0 + nb + j;
        if (n >= N) break;
        float v0 = acc[j][0].x + acc[j][0].y;
        float v1 = acc[j][1].x + acc[j][1].y;
        if (m < MKER) {
            __half2* yp = (__half2*)(g_y + (size_t)n * YSTR + m * C + co0);
            *yp = __floats2half2_rn(v0, v1);
        } else {
            *(float2*)(g_root + (size_t)n * C + co0) = make_float2(v0, v1);
        }
    }
}

// ---------------- node kernel (layers 1,2): warp per dst node, no atomics ----
__global__ void __launch_bounds__(256)
node_kernel(const float* __restrict__ bias, float* __restrict__ h_out, int N) {
    int n    = (blockIdx.x * blockDim.x + threadIdx.x) >> 5;
    int lane = threadIdx.x & 31;
    if (n >= N) return;
    int beg = g_rowptr[n], end = g_rowptr[n + 1];

    float2 acc = make_float2(0.f, 0.f);
    for (int e = beg; e < end; e++) {
        float4 r = __ldg(&g_rec[e]);          // uniform across warp
        int s = __float_as_int(r.x);
        float w[8]; int kk[8];
        basis8(r.y, r.z, r.w, w, kk);
        const __half* yb = g_y + (size_t)s * YSTR;
#pragma unroll
        for (int c = 0; c < 8; c++) {
            __half2 hv = __ldg((const __half2*)(yb + kk[c] * C) + lane);  // 128B row
            float2 v = __half22float2(hv);
            acc.x += w[c] * v.x;
            acc.y += w[c] * v.y;
        }
    }
    int   dg  = end - beg;
    float inv = 1.f / (float)(dg > 0 ? dg : 1);
    float2 rt = __ldg((const float2*)(g_root + (size_t)n * C) + lane);
    float2 bb = __ldg((const float2*)bias + lane);
    float2 res;
    res.x = fmaxf(acc.x * inv + rt.x + bb.x, 0.f);
    res.y = fmaxf(acc.y * inv + rt.y + bb.y, 0.f);
    ((float2*)h_out)[(size_t)n * 32 + lane] = res;
}

// ---------------- launch ----------------
extern "C" void kernel_launch(void* const* d_in, const int* in_sizes, int n_in,
                              void* d_out, int out_size) {
    const float* x     = (const float*)d_in[0];
    const int*   ei    = (const int*)d_in[1];
    const float* ea    = (const float*)d_in[2];
    const float* W0    = (const float*)d_in[3];
    const float* root0 = (const float*)d_in[4];
    const float* b0    = (const float*)d_in[5];
    const float* W1    = (const float*)d_in[6];
    const float* root1 = (const float*)d_in[7];
    const float* b1    = (const float*)d_in[8];
    const float* W2    = (const float*)d_in[9];
    const float* root2 = (const float*)d_in[10];
    const float* b2    = (const float*)d_in[11];
    float* out = (float*)d_out;

    int N = in_sizes[0] / 3;
    int E = in_sizes[1] / 2;
    const int* src = ei;
    const int* dst = ei + E;

    float* hP;
    cudaGetSymbolAddress((void**)&hP, g_h);

    int nodeBlocks = (N * 32 + 255) / 256;
    dim3 tGrid((N + T_NODES - 1) / T_NODES, MKER + 1);

    // ---- CSR + layer-0 scatter (one edge pass) ----
    zeroAll_kernel<<<(N * SSTR + 255) / 256, 256>>>(N);         // launch 0
    hist_kernel<<<(E + 255) / 256, 256>>>(dst, E);              // launch 1
    scan_kernel<<<1, 1024>>>(N);                                // launch 2
    build_kernel<<<(E + 255) / 256, 256>>>(src, dst, ea, x, E); // launch 3 (ncu)

    // ---- layer 0 ----
    l0_kernel<<<nodeBlocks, 256>>>(x, W0, root0, b0, N);

    // ---- layer 1 ----
    transform_kernel<<<tGrid, 256>>>(hP, W1, root1, N);
    node_kernel<<<nodeBlocks, 256>>>(b1, hP, N);

    // ---- layer 2 ----
    transform_kernel<<<tGrid, 256>>>(hP, W2, root2, N);
    node_kernel<<<nodeBlocks, 256>>>(b2, out, N);
}